// round 17
// baseline (speedup 1.0000x reference)
#include <cuda_runtime.h>
#include <cuda_fp16.h>
#include <mma.h>

using namespace nvcuda;

// ============================================================================
// FastAsyncGNN: 3-layer GCN
//   count -> scan(+reset) -> fill -> [HMMA-GEMM -> agg]x2 -> GEMM3(+bias)
// GEMM1/2: fp16 HMMA m16n16k16 (R15 form, 236.6us best).
// agg: THREE warps per node (32-feat stripe each) for 3x latency hiding.
// Shapes: N=50000, E=800000, F_IN=128, F_HID=96, F_OUT=40
// ============================================================================

#define NN 50000
#define EE 800000
#define NPAD 50048   // 391 blocks * 128 rows: wmma epilogue writes up to here

// -------- scratch (device globals; no allocation allowed) --------
__device__ int    g_deg[NN];        // zero at load; scan resets after reading
__device__ int    g_cur[NN];
__device__ int    g_rowptr[NN + 1];
__device__ float  g_dinv[NN];
__device__ __align__(8)  int2           g_cw[EE];        // (src, wgt-bits)
__device__ __align__(16) unsigned short g_h[NPAD * 96];  // fp16 bits (padded)
__device__ __align__(16) float          g_a[NN * 96];    // fp32

// ============================================================================
// CSR build
// ============================================================================
__global__ void count_kernel(const int* __restrict__ dst) {
    int e = blockIdx.x * blockDim.x + threadIdx.x;
    if (e < EE) atomicAdd(&g_deg[dst[e]], 1);
}

// single block, 1024 threads: exclusive scan of deg; dinv; zero cursors;
// resets deg to 0 so the next run's count starts clean (replay-safe).
__global__ void scan_kernel() {
    __shared__ int s[1024];
    int tid = threadIdx.x;
    const int per = (NN + 1023) / 1024;  // 49
    int start = tid * per;
    int end = start + per; if (end > NN) end = NN;
    int sum = 0;
    for (int i = start; i < end; i++) sum += g_deg[i];
    s[tid] = sum;
    __syncthreads();
    for (int off = 1; off < 1024; off <<= 1) {
        int v = s[tid];
        int u = (tid >= off) ? s[tid - off] : 0;
        __syncthreads();
        s[tid] = v + u;
        __syncthreads();
    }
    int run = (tid > 0) ? s[tid - 1] : 0;
    for (int i = start; i < end; i++) {
        int d = g_deg[i];
        g_rowptr[i] = run;
        run += d;
        g_dinv[i] = rsqrtf((float)(d + 1));
        g_cur[i] = 0;
        g_deg[i] = 0;   // self-reset for next run
    }
    if (tid == 1023) g_rowptr[NN] = s[1023];
}

__global__ void fill_kernel(const int* __restrict__ src, const int* __restrict__ dst) {
    int t = blockIdx.x * blockDim.x + threadIdx.x;
    int e0 = t * 2;
    if (e0 + 1 < EE) {
        int2 sp = *(const int2*)(src + e0);
        int2 dp = *(const int2*)(dst + e0);
        int p0 = atomicAdd(&g_cur[dp.x], 1);
        int p1 = atomicAdd(&g_cur[dp.y], 1);
        g_cw[g_rowptr[dp.x] + p0] =
            make_int2(sp.x, __float_as_int(g_dinv[sp.x] * g_dinv[dp.x]));
        g_cw[g_rowptr[dp.y] + p1] =
            make_int2(sp.y, __float_as_int(g_dinv[sp.y] * g_dinv[dp.y]));
    } else if (e0 < EE) {
        int sN = src[e0];
        int d = dst[e0];
        int p = atomicAdd(&g_cur[d], 1);
        g_cw[g_rowptr[d] + p] = make_int2(sN, __float_as_int(g_dinv[sN] * g_dinv[d]));
    }
}

// ============================================================================
// fp16 HMMA GEMM (R15 form): g_h[n,FO](fp16) = A[n,FI] @ W[FI,FO]
// A_==nullptr -> read g_a. BM=128 (8 warps x 16 rows), BK=32, m16n16k16.
// ============================================================================
template <int FI, int FO>
__global__ void __launch_bounds__(256)
gemm_h_kernel(const float* __restrict__ A_, const float* __restrict__ W, int n) {
    constexpr int BM = 128;
    constexpr int BK = 32;
    constexpr int NT = FO / 16;      // 6
    constexpr int LDA = BK + 8;      // 40 halves
    constexpr int LDC = 20;          // floats
    static_assert(FI % BK == 0 && FO % 16 == 0, "shape");

    const float* A = A_ ? A_ : (const float*)g_a;

    __shared__ __half As[BM][LDA];
    __shared__ __half Ws[BK][FO];
    __shared__ float  Cs[BM][LDC];

    int tid = threadIdx.x;
    int warp = tid >> 5;
    int row0 = blockIdx.x * BM;

    wmma::fragment<wmma::accumulator, 16, 16, 16, float> acc[NT];
#pragma unroll
    for (int t = 0; t < NT; t++) wmma::fill_fragment(acc[t], 0.f);

    for (int k0 = 0; k0 < FI; k0 += BK) {
#pragma unroll
        for (int q = tid; q < BM * (BK / 4); q += 256) {
            int row = q >> 3;
            int c4 = (q & 7) * 4;
            int gr = row0 + row;
            float4 v = make_float4(0.f, 0.f, 0.f, 0.f);
            if (gr < n) v = *(const float4*)(A + (size_t)gr * FI + k0 + c4);
            *(__half2*)&As[row][c4]     = __floats2half2_rn(v.x, v.y);
            *(__half2*)&As[row][c4 + 2] = __floats2half2_rn(v.z, v.w);
        }
#pragma unroll
        for (int q = tid; q < BK * (FO / 4); q += 256) {
            int kk = q / (FO / 4);
            int c4 = (q % (FO / 4)) * 4;
            float4 v = *(const float4*)(W + (size_t)(k0 + kk) * FO + c4);
            *(__half2*)&Ws[kk][c4]     = __floats2half2_rn(v.x, v.y);
            *(__half2*)&Ws[kk][c4 + 2] = __floats2half2_rn(v.z, v.w);
        }
        __syncthreads();

#pragma unroll
        for (int ks = 0; ks < BK / 16; ks++) {
            wmma::fragment<wmma::matrix_a, 16, 16, 16, __half, wmma::row_major> af;
            wmma::load_matrix_sync(af, &As[warp * 16][ks * 16], LDA);
#pragma unroll
            for (int t = 0; t < NT; t++) {
                wmma::fragment<wmma::matrix_b, 16, 16, 16, __half, wmma::row_major> bf;
                wmma::load_matrix_sync(bf, &Ws[ks * 16][t * 16], FO);
                wmma::mma_sync(acc[t], af, bf, acc[t]);
            }
        }
        __syncthreads();
    }

    // epilogue: per 16-col stripe via fp32 smem -> fp16 g_h (16B stores)
#pragma unroll
    for (int t = 0; t < NT; t++) {
        wmma::store_matrix_sync(&Cs[warp * 16][0], acc[t], LDC, wmma::mem_row_major);
        __syncthreads();
        int r = tid >> 1;
        int c0 = (tid & 1) * 8;
        unsigned short tmp[8];
#pragma unroll
        for (int c = 0; c < 8; c++)
            tmp[c] = __half_as_ushort(__float2half(Cs[r][c0 + c]));
        *(uint4*)&g_h[(size_t)(row0 + r) * FO + t * 16 + c0] = *(uint4*)tmp;
        __syncthreads();
    }
}

// ============================================================================
// Scalar fp32 GEMM (output projection): out = g_a @ W + bias
// ============================================================================
template <int FI, int FO, int CT, int TN, int RT, int TM>
__global__ void __launch_bounds__(256)
gemm_out_kernel(const float* __restrict__ W, const float* __restrict__ bias,
                float* __restrict__ C, int n) {
    constexpr int BM = RT * TM;  // 128
    constexpr int BK = 32;
    static_assert(CT * RT == 256 && CT * TN == FO && FO % 4 == 0, "shape");

    const float* A = (const float*)g_a;

    __shared__ float As[BK][BM + 1];
    __shared__ float Ws[BK][FO];

    int tid = threadIdx.x;
    int tx = tid % CT;
    int ty = tid / CT;
    int row0 = blockIdx.x * BM;

    float acc[TM][TN];
#pragma unroll
    for (int r = 0; r < TM; r++)
#pragma unroll
        for (int c = 0; c < TN; c++) acc[r][c] = 0.f;

    for (int k0 = 0; k0 < FI; k0 += BK) {
#pragma unroll
        for (int q = tid; q < BM * (BK / 4); q += 256) {
            int row = q >> 3;
            int c4 = (q & 7) * 4;
            int gr = row0 + row;
            float4 v = make_float4(0.f, 0.f, 0.f, 0.f);
            if (gr < n) v = *(const float4*)(A + (size_t)gr * FI + k0 + c4);
            As[c4 + 0][row] = v.x;
            As[c4 + 1][row] = v.y;
            As[c4 + 2][row] = v.z;
            As[c4 + 3][row] = v.w;
        }
#pragma unroll
        for (int q = tid; q < BK * (FO / 4); q += 256) {
            int kk = q / (FO / 4);
            int c4 = (q % (FO / 4)) * 4;
            *(float4*)&Ws[kk][c4] = *(const float4*)(W + (size_t)(k0 + kk) * FO + c4);
        }
        __syncthreads();

#pragma unroll
        for (int kk = 0; kk < BK; kk++) {
            float av[TM];
#pragma unroll
            for (int r = 0; r < TM; r++) av[r] = As[kk][ty * TM + r];
            float bv[TN];
#pragma unroll
            for (int c = 0; c < TN; c++) bv[c] = Ws[kk][tx * TN + c];
#pragma unroll
            for (int c = 0; c < TN; c++)
#pragma unroll
                for (int r = 0; r < TM; r++)
                    acc[r][c] = fmaf(av[r], bv[c], acc[r][c]);
        }
        __syncthreads();
    }

#pragma unroll
    for (int r = 0; r < TM; r++) {
        int gr = row0 + ty * TM + r;
        if (gr < n) {
            float* crow = C + (size_t)gr * FO + tx * TN;
#pragma unroll
            for (int c = 0; c < TN; c++)
                crow[c] = acc[r][c] + bias[tx * TN + c];
        }
    }
}

// ============================================================================
// Aggregation: THREE warps per node; warp p of node i owns feats
// [32p, 32p+32). Per edge: one 64B fp16 gather per warp (aligned).
// g_a[i] = relu(bias + dinv^2*h[i] + sum w*h[src]); accum fp32.
// ============================================================================
__device__ __forceinline__ float h2f(unsigned short u) {
    return __half2float(__ushort_as_half(u));
}

__global__ void __launch_bounds__(256)
agg_kernel(const float* __restrict__ bias) {
    int gw = (blockIdx.x * blockDim.x + threadIdx.x) >> 5;
    int lane = threadIdx.x & 31;
    if (gw >= 3 * NN) return;
    int i = gw / 3;
    int col = (gw - i * 3) * 32 + lane;   // feature column this lane owns

    const unsigned short* h = (const unsigned short*)g_h;
    float di = g_dinv[i];
    float a = di * di * h2f(h[(size_t)i * 96 + col]);

    int e = g_rowptr[i];
    int fin = g_rowptr[i + 1];
#pragma unroll 4
    for (; e < fin; e++) {
        int2 cw = g_cw[e];
        float w = __int_as_float(cw.y);
        a = fmaf(w, h2f(h[(size_t)cw.x * 96 + col]), a);
    }
    g_a[(size_t)i * 96 + col] = fmaxf(a + bias[col], 0.f);
}

// ============================================================================
// launch — pure kernel launches only (graph-capture safe)
// gemm1 is launch #4 (the ncu capture slot).
// ============================================================================
extern "C" void kernel_launch(void* const* d_in, const int* in_sizes, int n_in,
                              void* d_out, int out_size) {
    const float* x    = (const float*)d_in[0];
    const int*   ei   = (const int*)d_in[1];
    const float* W1   = (const float*)d_in[2];
    const float* b1   = (const float*)d_in[3];
    const float* W2   = (const float*)d_in[4];
    const float* b2   = (const float*)d_in[5];
    const float* Wout = (const float*)d_in[6];
    const float* bout = (const float*)d_in[7];
    float* out = (float*)d_out;

    const int* src = ei;       // edge_index[0]
    const int* dst = ei + EE;  // edge_index[1]

    const int count_blocks = (EE + 255) / 256;            // 3125
    const int fill_blocks  = (EE / 2 + 255) / 256;        // 1563
    const int gemm_blocks  = (NN + 127) / 128;            // 391
    const int agg_blocks   = (3 * NN * 32 + 255) / 256;   // 18750

    // ---- CSR build ----
    count_kernel<<<count_blocks, 256>>>(dst);
    scan_kernel<<<1, 1024>>>();
    fill_kernel<<<fill_blocks, 256>>>(src, dst);

    // ---- layer 1 (gemm1 = capture slot #4) ----
    gemm_h_kernel<128, 96><<<gemm_blocks, 256>>>(x, W1, NN);
    agg_kernel<<<agg_blocks, 256>>>(b1);

    // ---- layer 2 ----
    gemm_h_kernel<96, 96><<<gemm_blocks, 256>>>(nullptr, W2, NN);
    agg_kernel<<<agg_blocks, 256>>>(b2);

    // ---- output projection (fp32, exact) ----
    gemm_out_kernel<96, 40, 8, 5, 32, 4>
        <<<gemm_blocks, 256>>>(Wout, bout, out, NN);
}